// round 1
// baseline (speedup 1.0000x reference)
#include <cuda_runtime.h>
#include <stdint.h>

// Problem constants
#define N1 12800          // 100*128 elements of tm1
#define N2 25600          // 100*256 elements of tm2
#define NT 38400          // total
#define K1 6399           // (N1-1)/2  -> torch lower median index
#define K2 12799          // (N2-1)/2

// Scratch (device globals; no allocation allowed)
__device__ float        g_tm[NT];       // gathered tm1 | tm2
__device__ float        g_part[160];    // per-block partial sums of (tm-vmask)^2
__device__ unsigned int g_hist1[2048];  // pass-1 (top 11 bits) histogram for tm1
__device__ unsigned int g_hist2[2048];  // pass-1 histogram for tm2

// Order-preserving float -> uint mapping
__device__ __forceinline__ unsigned int mono(unsigned int u) {
    return u ^ ((unsigned int)((int)u >> 31) | 0x80000000u);
}
__device__ __forceinline__ float unmono(unsigned int k) {
    unsigned int u = (k & 0x80000000u) ? (k ^ 0x80000000u) : ~k;
    return __uint_as_float(u);
}

// ---------------------------------------------------------------------------
// Kernel 0: zero the pass-1 histograms (needed every graph replay)
// ---------------------------------------------------------------------------
__global__ void init_kernel() {
    int i = threadIdx.x;
    for (int b = i; b < 2048; b += 1024) {
        g_hist1[b] = 0u;
        g_hist2[b] = 0u;
    }
}

// ---------------------------------------------------------------------------
// Kernel 1: gather the 38400 scattered elements, accumulate per-block
// partial sums of (tm - vmask)^2, and build the pass-1 radix histograms
// with global atomics (full-grid parallelism).
// Grid: 150 blocks x 256 threads == 38400 exactly. Blocks 0..49 -> tm1.
// ---------------------------------------------------------------------------
__global__ void __launch_bounds__(256) gather_kernel(
    const float* __restrict__ c2, const float* __restrict__ c3,
    const float* __restrict__ vm1, const float* __restrict__ vm2)
{
    int i = blockIdx.x * 256 + threadIdx.x;

    float t, v;
    unsigned int* hist;
    if (i < N1) {
        // c2[b, c, 7, 7] with (b*128+c) == i, inner size 56*56=3136
        t = c2[i * 3136 + 399];      // 7*56+7 = 399
        v = vm1[i];
        hist = g_hist1;
    } else {
        int j = i - N1;
        // c3[b, c, 3, 3], inner size 28*28=784
        t = c3[j * 784 + 87];        // 3*28+3 = 87
        v = vm2[j];
        hist = g_hist2;
    }
    g_tm[i] = t;

    unsigned int key = mono(__float_as_uint(t));
    atomicAdd(&hist[key >> 21], 1u);   // top 11 bits

    float d = t - v;
    float s = d * d;

    // block reduce (256 threads = 8 warps)
    __shared__ float red[8];
    #pragma unroll
    for (int o = 16; o; o >>= 1) s += __shfl_down_sync(0xffffffffu, s, o);
    if ((threadIdx.x & 31) == 0) red[threadIdx.x >> 5] = s;
    __syncthreads();
    if (threadIdx.x < 32) {
        float r = (threadIdx.x < 8) ? red[threadIdx.x] : 0.0f;
        #pragma unroll
        for (int o = 4; o; o >>= 1) r += __shfl_down_sync(0xffffffffu, r, o);
        if (threadIdx.x == 0) g_part[blockIdx.x] = r;
    }
}

// ---------------------------------------------------------------------------
// Block-wide "find the bin containing rank k" over a shared histogram.
// Parallel scan (Hillis-Steele per-warp + warp-total scan), then each thread
// checks its own bins. nb in {1024, 2048}; blockDim.x == 1024.
// ---------------------------------------------------------------------------
__device__ unsigned int block_select(unsigned int* hist, int nb,
                                     unsigned int* warpbuf,
                                     unsigned int* k_sh, unsigned int* sel_sh)
{
    int tid  = threadIdx.x;
    int lane = tid & 31;
    int warp = tid >> 5;
    int bpt  = nb >> 10;          // bins per thread: 1 or 2
    int base = tid * bpt;

    unsigned int local = 0;
    for (int j = 0; j < bpt; j++) local += hist[base + j];

    // intra-warp inclusive scan
    unsigned int incl = local;
    #pragma unroll
    for (int o = 1; o < 32; o <<= 1) {
        unsigned int t = __shfl_up_sync(0xffffffffu, incl, o);
        if (lane >= o) incl += t;
    }
    if (lane == 31) warpbuf[warp] = incl;
    __syncthreads();
    if (warp == 0) {
        unsigned int w = warpbuf[lane];
        unsigned int wi = w;
        #pragma unroll
        for (int o = 1; o < 32; o <<= 1) {
            unsigned int t = __shfl_up_sync(0xffffffffu, wi, o);
            if (lane >= o) wi += t;
        }
        warpbuf[lane] = wi - w;   // exclusive warp offset
    }
    __syncthreads();

    unsigned int ex = (incl - local) + warpbuf[warp];  // thread-exclusive prefix
    unsigned int k = *k_sh;
    __syncthreads();

    unsigned int c = ex;
    for (int j = 0; j < bpt; j++) {
        unsigned int h = hist[base + j];
        if (k >= c && k < c + h) {
            *sel_sh = (unsigned int)(base + j);
            *k_sh   = k - c;
        }
        c += h;
    }
    __syncthreads();
    return *sel_sh;
}

// ---------------------------------------------------------------------------
// Exact k-th smallest (3-pass radix select: 11 + 11 + 10 bits).
// Pass 1 histogram was already built full-grid in gather_kernel.
// ---------------------------------------------------------------------------
__device__ unsigned int radix_select(const float* __restrict__ data, int n,
                                     unsigned int k0,
                                     const unsigned int* __restrict__ ghist,
                                     unsigned int* sh_hist, unsigned int* warpbuf,
                                     unsigned int* k_sh, unsigned int* sel_sh)
{
    int tid = threadIdx.x;

    // ---- pass 1: top 11 bits, histogram is in global memory
    for (int b = tid; b < 2048; b += 1024) sh_hist[b] = ghist[b];
    if (tid == 0) *k_sh = k0;
    __syncthreads();
    unsigned int d0 = block_select(sh_hist, 2048, warpbuf, k_sh, sel_sh);

    // ---- pass 2: bits [20:10] among elements matching prefix d0
    for (int b = tid; b < 2048; b += 1024) sh_hist[b] = 0u;
    __syncthreads();
    for (int i = tid; i < n; i += 1024) {
        unsigned int key = mono(__float_as_uint(data[i]));
        if ((key >> 21) == d0) atomicAdd(&sh_hist[(key >> 10) & 0x7FFu], 1u);
    }
    __syncthreads();
    unsigned int d1 = block_select(sh_hist, 2048, warpbuf, k_sh, sel_sh);
    unsigned int p21 = (d0 << 11) | d1;

    // ---- pass 3: bits [9:0]
    for (int b = tid; b < 1024; b += 1024) sh_hist[b] = 0u;
    __syncthreads();
    for (int i = tid; i < n; i += 1024) {
        unsigned int key = mono(__float_as_uint(data[i]));
        if ((key >> 10) == p21) atomicAdd(&sh_hist[key & 0x3FFu], 1u);
    }
    __syncthreads();
    unsigned int d2 = block_select(sh_hist, 1024, warpbuf, k_sh, sel_sh);

    return (p21 << 10) | d2;
}

// two-value block reduce; result valid in thread 0
__device__ void block_reduce2(float& a, float& b, float* red)
{
    int lane = threadIdx.x & 31;
    int warp = threadIdx.x >> 5;
    #pragma unroll
    for (int o = 16; o; o >>= 1) {
        a += __shfl_down_sync(0xffffffffu, a, o);
        b += __shfl_down_sync(0xffffffffu, b, o);
    }
    if (lane == 0) { red[warp] = a; red[32 + warp] = b; }
    __syncthreads();
    if (warp == 0) {
        a = red[lane];
        b = red[32 + lane];
        #pragma unroll
        for (int o = 16; o; o >>= 1) {
            a += __shfl_down_sync(0xffffffffu, a, o);
            b += __shfl_down_sync(0xffffffffu, b, o);
        }
    }
}

// ---------------------------------------------------------------------------
// Kernel 2 (single block, 1024 threads): reduce partials -> p,
// both exact medians, then q, then write [p, q].
// ---------------------------------------------------------------------------
__global__ void __launch_bounds__(1024) finalize_kernel(
    const float* __restrict__ am1, const float* __restrict__ am2,
    float* __restrict__ out)
{
    __shared__ unsigned int sh_hist[2048];
    __shared__ unsigned int warpbuf[32];
    __shared__ unsigned int k_sh, sel_sh;
    __shared__ float red[64];
    __shared__ float s_p;

    int tid = threadIdx.x;

    // --- p: reduce the 150 per-block partials (blocks 0..49 = tm1)
    float a1 = (tid < 50) ? g_part[tid] : 0.0f;
    float a2 = (tid >= 50 && tid < 150) ? g_part[tid] : 0.0f;
    block_reduce2(a1, a2, red);
    if (tid == 0) s_p = (sqrtf(a1) + sqrtf(a2)) * (1.0f / 38400.0f);
    __syncthreads();

    // --- exact medians
    unsigned int m1k = radix_select(g_tm,      N1, K1, g_hist1,
                                    sh_hist, warpbuf, &k_sh, &sel_sh);
    unsigned int m2k = radix_select(g_tm + N1, N2, K2, g_hist2,
                                    sh_hist, warpbuf, &k_sh, &sel_sh);
    float m1 = unmono(m1k);
    float m2 = unmono(m2k);

    // --- q: binarize + Frobenius norms against amasks
    float q1 = 0.0f, q2 = 0.0f;
    for (int i = tid; i < N1; i += 1024) {
        float b = (g_tm[i] < m1) ? 0.0f : 1.0f;
        float d = b - am1[i];
        q1 += d * d;
    }
    for (int i = tid; i < N2; i += 1024) {
        float b = (g_tm[N1 + i] < m2) ? 0.0f : 1.0f;
        float d = b - am2[i];
        q2 += d * d;
    }
    __syncthreads();   // protect `red` reuse
    block_reduce2(q1, q2, red);

    if (tid == 0) {
        out[0] = s_p;
        out[1] = (sqrtf(q1) + sqrtf(q2)) * (1.0f / 384.0f);
    }
}

// ---------------------------------------------------------------------------
extern "C" void kernel_launch(void* const* d_in, const int* in_sizes, int n_in,
                              void* d_out, int out_size)
{
    const float* c2  = (const float*)d_in[0];
    const float* c3  = (const float*)d_in[1];
    const float* vm1 = (const float*)d_in[2];
    const float* vm2 = (const float*)d_in[3];
    const float* am1 = (const float*)d_in[4];
    const float* am2 = (const float*)d_in[5];
    float* out = (float*)d_out;

    init_kernel<<<1, 1024>>>();
    gather_kernel<<<150, 256>>>(c2, c3, vm1, vm2);
    finalize_kernel<<<1, 1024>>>(am1, am2, out);
}